// round 1
// baseline (speedup 1.0000x reference)
#include <cuda_runtime.h>
#include <math.h>

#define TPB     256
#define MAX_S   (1 << 21)   // key space bound (flags / prefix arrays)
#define MAX_N   (1 << 21)
#define MAXB    16
#define C_IN    32
#define C_OUT   64
#define EPSV    1e-5f

// ---------------- device scratch (no allocations allowed) ----------------
__device__ int      g_flags[MAX_S];
__device__ int      g_prefix[MAX_S];
__device__ int      g_bsums[1024];
__device__ int      g_vkey[MAX_N];
__device__ float    g_S[C_IN * C_IN];       // sum of f f^T
__device__ float    g_fsum[C_IN];           // sum of f
__device__ unsigned g_start[MAXB * 3];      // per-batch min coord (uint bits, nonneg floats)
__device__ int      g_D[3];                 // voxel grid extents (max v + 1)
__device__ float    g_scale[C_OUT];
__device__ float    g_shift[C_OUT];
__device__ int      g_count[MAX_S];         // points per cluster
__device__ int      g_bcl[MAX_S];           // batch id per cluster
__device__ int      g_bcount[MAXB];         // clusters per batch

__device__ __forceinline__ int get_batch(int i, const int* soff, int B) {
    // searchsorted(offset, i, side='right'): first b with i < offset[b]
    int lo = 0, hi = B - 1;
    while (lo < hi) {
        int mid = (lo + hi) >> 1;
        if (i < soff[mid]) hi = mid; else lo = mid + 1;
    }
    return lo;
}

// ---------------- init: zero scratch + output ----------------
__global__ void k_init(float* out, long long nout) {
    long long idx = (long long)blockIdx.x * TPB + threadIdx.x;
    long long stride = (long long)gridDim.x * TPB;
    for (long long i = idx; i < nout; i += stride) out[i] = 0.f;
    for (long long i = idx; i < MAX_S; i += stride) { g_flags[i] = 0; g_count[i] = 0; }
    if (idx < C_IN * C_IN) g_S[idx] = 0.f;
    if (idx < C_IN)        g_fsum[idx] = 0.f;
    if (idx < MAXB * 3)    g_start[idx] = 0x7F800000u;  // +inf bits
    if (idx < 3)           g_D[idx] = 0;
    if (idx < MAXB)        g_bcount[idx] = 0;
}

// ---------------- pass 1: per-batch coord min + feature moments ----------------
__global__ __launch_bounds__(TPB) void k_stats(
    const float* __restrict__ coord, const float* __restrict__ feat,
    const int* __restrict__ offset, int N, int B, int nchunks)
{
    __shared__ float sf[256 * C_IN];          // 32 KB: 256 points x 32 ch
    __shared__ unsigned smin[MAXB * 3];
    __shared__ int soff[MAXB];
    int t = threadIdx.x;
    if (t < B) soff[t] = offset[t];
    if (t < B * 3) smin[t] = 0x7F800000u;
    __syncthreads();

    int a  = t >> 3;          // 0..31  (row of S)
    int b4 = (t & 7) * 4;     // 0..28  (4-col group of S)
    float s0 = 0.f, s1 = 0.f, s2 = 0.f, s3 = 0.f, fs = 0.f;

    for (int chunk = blockIdx.x; chunk < nchunks; chunk += gridDim.x) {
        int base = chunk * 256;
        // stage features (coalesced)
        for (int idx = t; idx < 256 * C_IN; idx += TPB) {
            int p = base + (idx >> 5);
            sf[idx] = (p < N) ? feat[(size_t)base * C_IN + idx] : 0.f;
        }
        // per-batch coord min
        int p = base + t;
        if (p < N) {
            int bb = get_batch(p, soff, B);
            atomicMin(&smin[bb * 3 + 0], __float_as_uint(coord[(size_t)p * 3 + 0]));
            atomicMin(&smin[bb * 3 + 1], __float_as_uint(coord[(size_t)p * 3 + 1]));
            atomicMin(&smin[bb * 3 + 2], __float_as_uint(coord[(size_t)p * 3 + 2]));
        }
        __syncthreads();
        // rank-256 update of S (each thread owns 4 entries)
        #pragma unroll 4
        for (int pp = 0; pp < 256; pp++) {
            float fa = sf[pp * C_IN + a];
            float4 fb = *(const float4*)&sf[pp * C_IN + b4];
            s0 += fa * fb.x; s1 += fa * fb.y; s2 += fa * fb.z; s3 += fa * fb.w;
            if ((t & 7) == 0) fs += fa;     // threads 0,8,... accumulate column sums
        }
        __syncthreads();
    }
    atomicAdd(&g_S[a * C_IN + b4 + 0], s0);
    atomicAdd(&g_S[a * C_IN + b4 + 1], s1);
    atomicAdd(&g_S[a * C_IN + b4 + 2], s2);
    atomicAdd(&g_S[a * C_IN + b4 + 3], s3);
    if ((t & 7) == 0) atomicAdd(&g_fsum[a], fs);
    __syncthreads();
    if (t < B * 3) atomicMin(&g_start[t], smin[t]);
}

// ---------------- BN affine params from moments ----------------
__global__ void k_finalize(const float* __restrict__ W, const float* __restrict__ gamma,
                           const float* __restrict__ beta, float Ninv)
{
    int j = threadIdx.x;
    if (j >= C_OUT) return;
    float mean = 0.f;
    for (int k = 0; k < C_IN; k++) mean += g_fsum[k] * W[k * C_OUT + j];
    mean *= Ninv;
    float ms = 0.f;
    for (int a = 0; a < C_IN; a++) {
        float wa = W[a * C_OUT + j];
        for (int b = 0; b < C_IN; b++) ms += g_S[a * C_IN + b] * wa * W[b * C_OUT + j];
    }
    ms *= Ninv;
    float var = ms - mean * mean;
    float inv = rsqrtf(var + EPSV);
    float sc = gamma[j] * inv;
    g_scale[j] = sc;
    g_shift[j] = beta[j] - mean * sc;
}

// ---------------- voxel extents D = max(v)+1 ----------------
__global__ __launch_bounds__(TPB) void k_vmax(
    const float* __restrict__ coord, const int* __restrict__ offset,
    const float* __restrict__ gsz, int N, int B)
{
    __shared__ int soff[MAXB];
    __shared__ float sst[MAXB * 3];
    __shared__ int smax[3];
    int t = threadIdx.x;
    if (t < B) soff[t] = offset[t];
    if (t < B * 3) sst[t] = __uint_as_float(g_start[t]);
    if (t < 3) smax[t] = 0;
    __syncthreads();
    float g = gsz[0];
    int m0 = 0, m1 = 0, m2 = 0;
    for (int p = blockIdx.x * TPB + t; p < N; p += gridDim.x * TPB) {
        int b = get_batch(p, soff, B);
        int v0 = (int)floorf(__fdiv_rn(coord[(size_t)p * 3 + 0] - sst[b * 3 + 0], g));
        int v1 = (int)floorf(__fdiv_rn(coord[(size_t)p * 3 + 1] - sst[b * 3 + 1], g));
        int v2 = (int)floorf(__fdiv_rn(coord[(size_t)p * 3 + 2] - sst[b * 3 + 2], g));
        m0 = max(m0, v0); m1 = max(m1, v1); m2 = max(m2, v2);
    }
    atomicMax(&smax[0], m0); atomicMax(&smax[1], m1); atomicMax(&smax[2], m2);
    __syncthreads();
    if (t < 3) atomicMax(&g_D[t], smax[t] + 1);
}

// ---------------- keys + occupancy flags ----------------
__global__ __launch_bounds__(TPB) void k_keys(
    const float* __restrict__ coord, const int* __restrict__ offset,
    const float* __restrict__ gsz, int N, int B)
{
    __shared__ int soff[MAXB];
    __shared__ float sst[MAXB * 3];
    __shared__ int sD[3];
    int t = threadIdx.x;
    if (t < B) soff[t] = offset[t];
    if (t < B * 3) sst[t] = __uint_as_float(g_start[t]);
    if (t < 3) sD[t] = g_D[t];
    __syncthreads();
    float g = gsz[0];
    int p = blockIdx.x * TPB + t;
    if (p >= N) return;
    int b = get_batch(p, soff, B);
    int v0 = (int)floorf(__fdiv_rn(coord[(size_t)p * 3 + 0] - sst[b * 3 + 0], g));
    int v1 = (int)floorf(__fdiv_rn(coord[(size_t)p * 3 + 1] - sst[b * 3 + 1], g));
    int v2 = (int)floorf(__fdiv_rn(coord[(size_t)p * 3 + 2] - sst[b * 3 + 2], g));
    int key = ((b * sD[0] + v0) * sD[1] + v1) * sD[2] + v2;
    if (key < 0) key = 0;
    if (key >= MAX_S) key = MAX_S - 1;
    g_flags[key] = 1;
    g_vkey[p] = key;
}

// ---------------- exclusive scan of flags: per-block stage ----------------
__global__ __launch_bounds__(TPB) void k_scanA() {
    __shared__ int sh[TPB];
    int t = threadIdx.x;
    int base = blockIdx.x * 2048 + t * 8;
    int4 u0 = *(const int4*)&g_flags[base];
    int4 u1 = *(const int4*)&g_flags[base + 4];
    int v[8] = {u0.x, u0.y, u0.z, u0.w, u1.x, u1.y, u1.z, u1.w};
    int sum = 0;
    #pragma unroll
    for (int i = 0; i < 8; i++) { int x = v[i]; v[i] = sum; sum += x; }
    sh[t] = sum;
    __syncthreads();
    for (int off = 1; off < TPB; off <<= 1) {
        int x = (t >= off) ? sh[t - off] : 0;
        __syncthreads();
        sh[t] += x;
        __syncthreads();
    }
    int excl = sh[t] - sum;
    #pragma unroll
    for (int i = 0; i < 8; i++) v[i] += excl;
    *(int4*)&g_prefix[base]     = make_int4(v[0], v[1], v[2], v[3]);
    *(int4*)&g_prefix[base + 4] = make_int4(v[4], v[5], v[6], v[7]);
    if (t == TPB - 1) g_bsums[blockIdx.x] = sh[t];
}

// ---------------- exclusive scan of block sums (1024) ----------------
__global__ void k_scanB() {
    __shared__ int sh[1024];
    int t = threadIdx.x;
    int own = g_bsums[t];
    sh[t] = own;
    __syncthreads();
    for (int off = 1; off < 1024; off <<= 1) {
        int x = (t >= off) ? sh[t - off] : 0;
        __syncthreads();
        sh[t] += x;
        __syncthreads();
    }
    g_bsums[t] = sh[t] - own;   // exclusive
}

// ---------------- fused: inverse, coord sums, GEMM + BN + ReLU + segment max ----------------
__global__ __launch_bounds__(TPB) void k_main(
    const float* __restrict__ coord, const float* __restrict__ feat,
    const int* __restrict__ offset, const float* __restrict__ W,
    int N, int B, float* out_coord, float* out_feat, float* out_inv)
{
    __shared__ float Wsh[C_IN * C_OUT];
    __shared__ float ssc[C_OUT], ssh[C_OUT];
    __shared__ int soff[MAXB];
    int t = threadIdx.x;
    for (int i = t; i < C_IN * C_OUT; i += TPB) Wsh[i] = W[i];
    if (t < C_OUT) { ssc[t] = g_scale[t]; ssh[t] = g_shift[t]; }
    if (t < B) soff[t] = offset[t];
    __syncthreads();

    int p = blockIdx.x * TPB + t;
    if (p >= N) return;

    int key = g_vkey[p];
    int cid = g_prefix[key] + g_bsums[key >> 11];
    out_inv[p] = (float)cid;

    int b = get_batch(p, soff, B);
    g_bcl[cid] = b;                       // same value for all points in cluster
    atomicAdd(&g_count[cid], 1);
    atomicAdd(&out_coord[3 * cid + 0], coord[(size_t)p * 3 + 0]);
    atomicAdd(&out_coord[3 * cid + 1], coord[(size_t)p * 3 + 1]);
    atomicAdd(&out_coord[3 * cid + 2], coord[(size_t)p * 3 + 2]);

    float f[C_IN];
    const float4* fr = (const float4*)(feat + (size_t)p * C_IN);
    #pragma unroll
    for (int i = 0; i < 8; i++) {
        float4 x = fr[i];
        f[4*i] = x.x; f[4*i+1] = x.y; f[4*i+2] = x.z; f[4*i+3] = x.w;
    }

    unsigned* of = (unsigned*)(out_feat + (size_t)cid * C_OUT);
    #pragma unroll
    for (int jt = 0; jt < C_OUT; jt += 32) {
        float acc[32];
        #pragma unroll
        for (int j = 0; j < 32; j++) acc[j] = 0.f;
        #pragma unroll
        for (int k = 0; k < C_IN; k++) {
            float fk = f[k];
            #pragma unroll
            for (int j4 = 0; j4 < 8; j4++) {
                float4 w = *(const float4*)&Wsh[k * C_OUT + jt + j4 * 4];
                acc[j4*4+0] += fk * w.x; acc[j4*4+1] += fk * w.y;
                acc[j4*4+2] += fk * w.z; acc[j4*4+3] += fk * w.w;
            }
        }
        #pragma unroll
        for (int j = 0; j < 32; j++) {
            float h = fmaxf(acc[j] * ssc[jt + j] + ssh[jt + j], 0.f);
            atomicMax(&of[jt + j], __float_as_uint(h));   // relu(h) >= 0: uint order == float order
        }
    }
}

// ---------------- per-cluster: mean coords + batch histogram ----------------
__global__ void k_post(float* out_coord, int M) {
    int c = blockIdx.x * TPB + threadIdx.x;
    if (c >= M) return;
    float cnt = (float)g_count[c];
    out_coord[3 * c + 0] = out_coord[3 * c + 0] / cnt;
    out_coord[3 * c + 1] = out_coord[3 * c + 1] / cnt;
    out_coord[3 * c + 2] = out_coord[3 * c + 2] / cnt;
    atomicAdd(&g_bcount[g_bcl[c]], 1);
}

// ---------------- offset_out: cumsum of per-batch cluster counts ----------------
__global__ void k_offsets(float* out_off, int B) {
    int run = 0;
    for (int b = 0; b < B; b++) { run += g_bcount[b]; out_off[b] = (float)run; }
}

// ---------------- launch ----------------
extern "C" void kernel_launch(void* const* d_in, const int* in_sizes, int n_in,
                              void* d_out, int out_size)
{
    const float* coord  = (const float*)d_in[0];
    const float* feat   = (const float*)d_in[1];
    const int*   offset = (const int*)d_in[2];
    const float* W      = (const float*)d_in[3];
    const float* gamma  = (const float*)d_in[4];
    const float* beta   = (const float*)d_in[5];
    const float* gsz    = (const float*)d_in[6];

    int N = in_sizes[0] / 3;
    int B = in_sizes[2];
    long long M = ((long long)out_size - B - N) / 67;   // 3M + 64M + B + N = out_size
    if (M < 0) M = 0;

    float* out       = (float*)d_out;
    float* out_coord = out;
    float* out_feat  = out + 3 * M;
    float* out_off   = out + 67 * M;
    float* out_inv   = out_off + B;

    int nchunks = (N + 255) / 256;
    int ngrid   = (N + TPB - 1) / TPB;

    k_init<<<4096, TPB>>>(out, (long long)out_size);
    k_stats<<<1024, TPB>>>(coord, feat, offset, N, B, nchunks);
    k_finalize<<<1, 64>>>(W, gamma, beta, 1.0f / (float)N);
    k_vmax<<<1024, TPB>>>(coord, offset, gsz, N, B);
    k_keys<<<ngrid, TPB>>>(coord, offset, gsz, N, B);
    k_scanA<<<MAX_S / 2048, TPB>>>();
    k_scanB<<<1, 1024>>>();
    k_main<<<ngrid, TPB>>>(coord, feat, offset, W, N, B, out_coord, out_feat, out_inv);
    if (M > 0) k_post<<<(int)((M + TPB - 1) / TPB), TPB>>>(out_coord, (int)M);
    k_offsets<<<1, 1>>>(out_off, B);
}

// round 5
// speedup vs baseline: 1.2058x; 1.2058x over previous
#include <cuda_runtime.h>
#include <math.h>

#define TPB     256
#define MAX_S   (1 << 21)   // key space bound
#define MAX_N   (1 << 21)
#define MAXB    16
#define C_IN    32
#define C_OUT   64
#define EPSV    1e-5f

// ---------------- device scratch ----------------
__device__ __align__(16) int g_flags[MAX_S];
__device__ __align__(16) int g_prefix[MAX_S];
__device__ __align__(16) int g_count[MAX_S];   // points per cluster
__device__ __align__(16) int g_fill[MAX_S];    // scatter cursors
__device__ __align__(16) int g_bsums[1024];
__device__ __align__(16) int g_vkey[MAX_N];    // key per point
__device__ __align__(16) int g_cid[MAX_N];     // cluster id per point
__device__ __align__(16) int g_sorted[MAX_N];  // point ids sorted by cluster
__device__ float    g_S[C_IN * C_IN];
__device__ float    g_fsum[C_IN];
__device__ unsigned g_start[MAXB * 3];
__device__ int      g_D[3];
__device__ float    g_scale[C_OUT];
__device__ float    g_shift[C_OUT];
__device__ int      g_bcount[MAXB];

__device__ __forceinline__ int get_batch(int i, const int* soff, int B) {
    int lo = 0, hi = B - 1;
    while (lo < hi) { int mid = (lo + hi) >> 1; if (i < soff[mid]) hi = mid; else lo = mid + 1; }
    return lo;
}

// ---------------- init scratch ----------------
__global__ void k_init() {
    int idx = blockIdx.x * TPB + threadIdx.x;
    int stride = gridDim.x * TPB;
    for (int i = idx; i < MAX_S / 4; i += stride) {
        ((int4*)g_flags)[i] = make_int4(0, 0, 0, 0);
        ((int4*)g_count)[i] = make_int4(0, 0, 0, 0);
        ((int4*)g_fill)[i]  = make_int4(0, 0, 0, 0);
    }
    if (idx < C_IN * C_IN) g_S[idx] = 0.f;
    if (idx < C_IN)        g_fsum[idx] = 0.f;
    if (idx < MAXB * 3)    g_start[idx] = 0x7F800000u;
    if (idx < 3)           g_D[idx] = 0;
    if (idx < MAXB)        g_bcount[idx] = 0;
}

// ---------------- pass 1: per-batch coord min + feature moments (warp-per-point) ----------------
__global__ __launch_bounds__(TPB) void k_stats(
    const float* __restrict__ coord, const float* __restrict__ feat,
    const int* __restrict__ offset, int N, int B, int nchunks)
{
    __shared__ __align__(16) float sf[256 * C_IN];   // 32 KB staging / reduction buffer
    __shared__ unsigned smin[MAXB * 3];
    __shared__ int soff[MAXB];
    int t = threadIdx.x, lane = t & 31, w = t >> 5;
    if (t < B) soff[t] = offset[t];
    if (t < B * 3) smin[t] = 0x7F800000u;
    __syncthreads();

    float acc[C_IN];
    #pragma unroll
    for (int i = 0; i < C_IN; i++) acc[i] = 0.f;
    float fsum_loc = 0.f;

    const float4* f4 = (const float4*)feat;
    for (int chunk = blockIdx.x; chunk < nchunks; chunk += gridDim.x) {
        int base = chunk * 256;
        float4* sf4 = (float4*)sf;
        #pragma unroll
        for (int i = 0; i < 8; i++) {
            int idx = t + i * 256;
            long long g = (long long)base * 8 + idx;
            sf4[idx] = (g < (long long)N * 8) ? f4[g] : make_float4(0.f, 0.f, 0.f, 0.f);
        }
        int p = base + t;
        if (p < N) {
            int bb = get_batch(p, soff, B);
            atomicMin(&smin[bb * 3 + 0], __float_as_uint(coord[(size_t)p * 3 + 0]));
            atomicMin(&smin[bb * 3 + 1], __float_as_uint(coord[(size_t)p * 3 + 1]));
            atomicMin(&smin[bb * 3 + 2], __float_as_uint(coord[(size_t)p * 3 + 2]));
        }
        __syncthreads();
        // warp w handles points [w*32, (w+1)*32): lane owns S row `lane`
        #pragma unroll 2
        for (int j = 0; j < 32; j++) {
            int pp = w * 32 + j;
            float fa = sf[pp * C_IN + lane];
            fsum_loc += fa;
            #pragma unroll
            for (int i4 = 0; i4 < 8; i4++) {
                float4 q = *(const float4*)&sf[pp * C_IN + i4 * 4];   // broadcast LDS.128
                acc[i4 * 4 + 0] = fmaf(fa, q.x, acc[i4 * 4 + 0]);
                acc[i4 * 4 + 1] = fmaf(fa, q.y, acc[i4 * 4 + 1]);
                acc[i4 * 4 + 2] = fmaf(fa, q.z, acc[i4 * 4 + 2]);
                acc[i4 * 4 + 3] = fmaf(fa, q.w, acc[i4 * 4 + 3]);
            }
        }
        __syncthreads();
    }
    // per-warp partials -> shared -> block sum -> global atomics
    #pragma unroll
    for (int i = 0; i < C_IN; i++) sf[w * 1024 + lane * C_IN + i] = acc[i];
    atomicAdd(&g_fsum[lane], fsum_loc);
    __syncthreads();
    #pragma unroll
    for (int r = 0; r < 4; r++) {
        int j = t * 4 + r;                       // S entry 0..1023 (row = j>>5, col = j&31)
        float s = 0.f;
        #pragma unroll
        for (int ww = 0; ww < 8; ww++) s += sf[ww * 1024 + j];
        atomicAdd(&g_S[j], s);
    }
    if (t < B * 3) atomicMin(&g_start[t], smin[t]);
}

// ---------------- BN affine params ----------------
__global__ void k_finalize(const float* __restrict__ W, const float* __restrict__ gamma,
                           const float* __restrict__ beta, float Ninv)
{
    int j = threadIdx.x;
    if (j >= C_OUT) return;
    float mean = 0.f;
    for (int k = 0; k < C_IN; k++) mean += g_fsum[k] * W[k * C_OUT + j];
    mean *= Ninv;
    float ms = 0.f;
    for (int a = 0; a < C_IN; a++) {
        float wa = W[a * C_OUT + j];
        for (int b = 0; b < C_IN; b++) ms += g_S[a * C_IN + b] * wa * W[b * C_OUT + j];
    }
    ms *= Ninv;
    float var = fmaxf(ms - mean * mean, 0.f);
    float inv = rsqrtf(var + EPSV);
    float sc = gamma[j] * inv;
    g_scale[j] = sc;
    g_shift[j] = beta[j] - mean * sc;
}

// ---------------- voxel extents ----------------
__global__ __launch_bounds__(TPB) void k_vmax(
    const float* __restrict__ coord, const int* __restrict__ offset,
    const float* __restrict__ gsz, int N, int B)
{
    __shared__ int soff[MAXB];
    __shared__ float sst[MAXB * 3];
    __shared__ int smax[3];
    int t = threadIdx.x;
    if (t < B) soff[t] = offset[t];
    if (t < B * 3) sst[t] = __uint_as_float(g_start[t]);
    if (t < 3) smax[t] = 0;
    __syncthreads();
    float g = gsz[0];
    int m0 = 0, m1 = 0, m2 = 0;
    for (int p = blockIdx.x * TPB + t; p < N; p += gridDim.x * TPB) {
        int b = get_batch(p, soff, B);
        int v0 = (int)floorf(__fdiv_rn(coord[(size_t)p * 3 + 0] - sst[b * 3 + 0], g));
        int v1 = (int)floorf(__fdiv_rn(coord[(size_t)p * 3 + 1] - sst[b * 3 + 1], g));
        int v2 = (int)floorf(__fdiv_rn(coord[(size_t)p * 3 + 2] - sst[b * 3 + 2], g));
        m0 = max(m0, v0); m1 = max(m1, v1); m2 = max(m2, v2);
    }
    atomicMax(&smax[0], m0); atomicMax(&smax[1], m1); atomicMax(&smax[2], m2);
    __syncthreads();
    if (t < 3) atomicMax(&g_D[t], smax[t] + 1);
}

// ---------------- keys + occupancy flags ----------------
__global__ __launch_bounds__(TPB) void k_keys(
    const float* __restrict__ coord, const int* __restrict__ offset,
    const float* __restrict__ gsz, int N, int B)
{
    __shared__ int soff[MAXB];
    __shared__ float sst[MAXB * 3];
    __shared__ int sD[3];
    int t = threadIdx.x;
    if (t < B) soff[t] = offset[t];
    if (t < B * 3) sst[t] = __uint_as_float(g_start[t]);
    if (t < 3) sD[t] = g_D[t];
    __syncthreads();
    float g = gsz[0];
    int p = blockIdx.x * TPB + t;
    if (p >= N) return;
    int b = get_batch(p, soff, B);
    int v0 = (int)floorf(__fdiv_rn(coord[(size_t)p * 3 + 0] - sst[b * 3 + 0], g));
    int v1 = (int)floorf(__fdiv_rn(coord[(size_t)p * 3 + 1] - sst[b * 3 + 1], g));
    int v2 = (int)floorf(__fdiv_rn(coord[(size_t)p * 3 + 2] - sst[b * 3 + 2], g));
    int key = ((b * sD[0] + v0) * sD[1] + v1) * sD[2] + v2;
    if (key < 0) key = 0;
    if (key >= MAX_S) key = MAX_S - 1;
    g_flags[key] = 1;
    g_vkey[p] = key;
}

// ---------------- exclusive scan: per-block stage ----------------
// mode 0: scan g_flags -> g_prefix ; mode 1: scan g_count -> g_prefix
// NOTE: device symbols are referenced INSIDE device code only (host-side
// symbol addresses are shadow addresses — passing them as args was the R3/R4 bug).
__global__ __launch_bounds__(TPB) void k_scanA(int mode) {
    const int* in = (mode == 0) ? g_flags : g_count;
    int* out = g_prefix;
    __shared__ int sh[TPB];
    int t = threadIdx.x;
    int base = blockIdx.x * 2048 + t * 8;
    int4 u0 = *(const int4*)&in[base];
    int4 u1 = *(const int4*)&in[base + 4];
    int v[8] = {u0.x, u0.y, u0.z, u0.w, u1.x, u1.y, u1.z, u1.w};
    int sum = 0;
    #pragma unroll
    for (int i = 0; i < 8; i++) { int x = v[i]; v[i] = sum; sum += x; }
    sh[t] = sum;
    __syncthreads();
    for (int off = 1; off < TPB; off <<= 1) {
        int x = (t >= off) ? sh[t - off] : 0;
        __syncthreads();
        sh[t] += x;
        __syncthreads();
    }
    int excl = sh[t] - sum;
    #pragma unroll
    for (int i = 0; i < 8; i++) v[i] += excl;
    *(int4*)&out[base]     = make_int4(v[0], v[1], v[2], v[3]);
    *(int4*)&out[base + 4] = make_int4(v[4], v[5], v[6], v[7]);
    if (t == TPB - 1) g_bsums[blockIdx.x] = sh[t];
}

__global__ void k_scanB() {
    __shared__ int sh[1024];
    int t = threadIdx.x;
    int own = g_bsums[t];
    sh[t] = own;
    __syncthreads();
    for (int off = 1; off < 1024; off <<= 1) {
        int x = (t >= off) ? sh[t - off] : 0;
        __syncthreads();
        sh[t] += x;
        __syncthreads();
    }
    g_bsums[t] = sh[t] - own;
}

// ---------------- cluster id per point + histogram + inverse output ----------------
__global__ __launch_bounds__(TPB) void k_cid(int N, float* __restrict__ out_inv) {
    int p = blockIdx.x * TPB + threadIdx.x;
    if (p >= N) return;
    int key = g_vkey[p];
    int cid = g_prefix[key] + g_bsums[key >> 11];
    g_cid[p] = cid;
    out_inv[p] = (float)cid;
    atomicAdd(&g_count[cid], 1);
}

// ---------------- scatter: sort point ids by cluster ----------------
__global__ __launch_bounds__(TPB) void k_scatter(int N) {
    int p = blockIdx.x * TPB + threadIdx.x;
    if (p >= N) return;
    int cid = g_cid[p];
    int pos = g_prefix[cid] + g_bsums[cid >> 11] + atomicAdd(&g_fill[cid], 1);
    g_sorted[pos] = p;
}

// ---------------- pool: warp per cluster; GEMM + BN + ReLU + max, coord mean ----------------
__global__ __launch_bounds__(TPB) void k_pool(
    const float* __restrict__ coord, const float* __restrict__ feat,
    const int* __restrict__ offset, const float* __restrict__ W,
    int M, int B, float* __restrict__ out_coord, float* __restrict__ out_feat)
{
    __shared__ __align__(16) float Wsh[C_IN * C_OUT];
    __shared__ __align__(16) float sbuf[8][2][32];
    __shared__ float ssc[C_OUT], ssh[C_OUT];
    __shared__ int soff[MAXB];
    int t = threadIdx.x, lane = t & 31, w = t >> 5;
    for (int i = t; i < C_IN * C_OUT; i += TPB) Wsh[i] = W[i];
    if (t < C_OUT) { ssc[t] = g_scale[t]; ssh[t] = g_shift[t]; }
    if (t < B) soff[t] = offset[t];
    __syncthreads();

    float Wr0[C_IN], Wr1[C_IN];
    #pragma unroll
    for (int k = 0; k < C_IN; k++) {
        Wr0[k] = Wsh[k * C_OUT + lane];
        Wr1[k] = Wsh[k * C_OUT + lane + 32];
    }
    float sc0 = ssc[lane], sh0 = ssh[lane], sc1 = ssc[lane + 32], sh1 = ssh[lane + 32];

    int c = blockIdx.x * 8 + w;
    if (c >= M) return;
    int s = g_prefix[c] + g_bsums[c >> 11];
    int n = max(g_count[c], 1);

    float mx0 = 0.f, mx1 = 0.f, cacc = 0.f;

    int idxc = g_sorted[s];
    float flc = feat[(size_t)idxc * C_IN + lane];
    float crc = (lane < 3) ? coord[(size_t)idxc * 3 + lane] : 0.f;

    for (int i = 0; i < n; i++) {
        int idxn = idxc; float fln = flc, crn = crc;
        if (i + 1 < n) {
            idxn = g_sorted[s + i + 1];
            fln = feat[(size_t)idxn * C_IN + lane];
            crn = (lane < 3) ? coord[(size_t)idxn * 3 + lane] : 0.f;
        }
        sbuf[w][i & 1][lane] = flc;
        __syncwarp();
        const float* fb = sbuf[w][i & 1];
        float h0 = 0.f, h1 = 0.f;
        #pragma unroll
        for (int i4 = 0; i4 < 8; i4++) {
            float4 f = *(const float4*)&fb[i4 * 4];
            h0 = fmaf(f.x, Wr0[i4 * 4 + 0], h0); h1 = fmaf(f.x, Wr1[i4 * 4 + 0], h1);
            h0 = fmaf(f.y, Wr0[i4 * 4 + 1], h0); h1 = fmaf(f.y, Wr1[i4 * 4 + 1], h1);
            h0 = fmaf(f.z, Wr0[i4 * 4 + 2], h0); h1 = fmaf(f.z, Wr1[i4 * 4 + 2], h1);
            h0 = fmaf(f.w, Wr0[i4 * 4 + 3], h0); h1 = fmaf(f.w, Wr1[i4 * 4 + 3], h1);
        }
        h0 = fmaxf(fmaf(h0, sc0, sh0), 0.f);
        h1 = fmaxf(fmaf(h1, sc1, sh1), 0.f);
        mx0 = fmaxf(mx0, h0);
        mx1 = fmaxf(mx1, h1);
        cacc += crc;
        idxc = idxn; flc = fln; crc = crn;
        __syncwarp();
    }
    out_feat[(size_t)c * C_OUT + lane]      = mx0;
    out_feat[(size_t)c * C_OUT + lane + 32] = mx1;
    if (lane < 3) out_coord[(size_t)c * 3 + lane] = cacc / (float)n;
    if (lane == 0) {
        int b = get_batch(g_sorted[s], soff, B);
        atomicAdd(&g_bcount[b], 1);
    }
}

// ---------------- offsets ----------------
__global__ void k_offsets(float* out_off, int B) {
    int run = 0;
    for (int b = 0; b < B; b++) { run += g_bcount[b]; out_off[b] = (float)run; }
}

// ---------------- launch ----------------
extern "C" void kernel_launch(void* const* d_in, const int* in_sizes, int n_in,
                              void* d_out, int out_size)
{
    const float* coord  = (const float*)d_in[0];
    const float* feat   = (const float*)d_in[1];
    const int*   offset = (const int*)d_in[2];
    const float* W      = (const float*)d_in[3];
    const float* gamma  = (const float*)d_in[4];
    const float* beta   = (const float*)d_in[5];
    const float* gsz    = (const float*)d_in[6];

    int N = in_sizes[0] / 3;
    int B = in_sizes[2];
    long long M = ((long long)out_size - B - N) / 67;
    if (M < 0) M = 0;

    float* out       = (float*)d_out;
    float* out_coord = out;
    float* out_feat  = out + 3 * M;
    float* out_off   = out + 67 * M;
    float* out_inv   = out_off + B;

    int nchunks = (N + 255) / 256;
    int ngrid   = (N + TPB - 1) / TPB;

    k_init<<<2048, TPB>>>();
    k_stats<<<1024, TPB>>>(coord, feat, offset, N, B, nchunks);
    k_finalize<<<1, 64>>>(W, gamma, beta, 1.0f / (float)N);
    k_vmax<<<1024, TPB>>>(coord, offset, gsz, N, B);
    k_keys<<<ngrid, TPB>>>(coord, offset, gsz, N, B);
    k_scanA<<<MAX_S / 2048, TPB>>>(0);
    k_scanB<<<1, 1024>>>();
    k_cid<<<ngrid, TPB>>>(N, out_inv);
    k_scanA<<<MAX_S / 2048, TPB>>>(1);
    k_scanB<<<1, 1024>>>();
    k_scatter<<<ngrid, TPB>>>(N);
    if (M > 0) k_pool<<<(int)((M + 7) / 8), TPB>>>(coord, feat, offset, W, (int)M, B, out_coord, out_feat);
    k_offsets<<<1, 1>>>(out_off, B);
}